// round 5
// baseline (speedup 1.0000x reference)
#include <cuda_runtime.h>
#include <cuda_bf16.h>
#include <cstdint>
#include <math.h>

#define SEQL 2048
#define HID  2048
#define NH   32
#define NKV  8
#define HD   64
#define QKVN 3072
#define GK   2048

// ---------------------------------------------------------------------------
// Scratch (device globals; no allocations allowed)
// ---------------------------------------------------------------------------
__device__ __nv_bfloat16  g_hid_hi[SEQL * HID];
__device__ __nv_bfloat16  g_hid_lo[SEQL * HID];
__device__ __nv_bfloat16  g_wqkvT_hi[QKVN * GK];
__device__ __nv_bfloat16  g_wqkvT_lo[QKVN * GK];
__device__ __nv_bfloat16  g_woT_hi[HID * GK];
__device__ __nv_bfloat16  g_woT_lo[HID * GK];
__device__ __nv_bfloat16  g_attn_hi[SEQL * HID];
__device__ __nv_bfloat16  g_attn_lo[SEQL * HID];
__device__ __nv_bfloat16  g_qh[SEQL * NH * HD];
__device__ __nv_bfloat16  g_ql[SEQL * NH * HD];
__device__ __nv_bfloat16  g_kh[SEQL * NKV * HD];
__device__ __nv_bfloat16  g_kl[SEQL * NKV * HD];
__device__ __nv_bfloat16  g_vh[SEQL * NKV * HD];
__device__ __nv_bfloat16  g_vl[SEQL * NKV * HD];

// ---------------------------------------------------------------------------
// PTX helpers (baseline sm_80+ only)
// ---------------------------------------------------------------------------
__device__ __forceinline__ uint32_t smem_u32(const void* p) {
    uint32_t a;
    asm("{ .reg .u64 t; cvta.to.shared.u64 t, %1; cvt.u32.u64 %0, t; }" : "=r"(a) : "l"(p));
    return a;
}
#define LDMX4(r, addr) \
    asm volatile("ldmatrix.sync.aligned.m8n8.x4.shared.b16 {%0,%1,%2,%3}, [%4];" \
        : "=r"((r)[0]), "=r"((r)[1]), "=r"((r)[2]), "=r"((r)[3]) : "r"(addr))
#define LDMX4T(r, addr) \
    asm volatile("ldmatrix.sync.aligned.m8n8.x4.trans.shared.b16 {%0,%1,%2,%3}, [%4];" \
        : "=r"((r)[0]), "=r"((r)[1]), "=r"((r)[2]), "=r"((r)[3]) : "r"(addr))
#define CP_ASYNC16(dst, src) \
    asm volatile("cp.async.cg.shared.global [%0], [%1], 16;" :: "r"(dst), "l"(src))
#define CP_COMMIT() asm volatile("cp.async.commit_group;")
#define CP_WAIT1()  asm volatile("cp.async.wait_group 1;")
#define CP_WAIT0()  asm volatile("cp.async.wait_group 0;")

__device__ __forceinline__ void mma_bf16(float* d, const uint32_t* a, const uint32_t* b) {
    asm volatile("mma.sync.aligned.m16n8k16.row.col.f32.bf16.bf16.f32 "
        "{%0,%1,%2,%3}, {%4,%5,%6,%7}, {%8,%9}, {%0,%1,%2,%3};"
        : "+f"(d[0]), "+f"(d[1]), "+f"(d[2]), "+f"(d[3])
        : "r"(a[0]), "r"(a[1]), "r"(a[2]), "r"(a[3]), "r"(b[0]), "r"(b[1]));
}

__device__ __forceinline__ void split_pack(float x, float y, uint32_t& hi, uint32_t& lo) {
    __nv_bfloat16 hx = __float2bfloat16(x), hy = __float2bfloat16(y);
    __nv_bfloat162 h2; h2.x = hx; h2.y = hy;
    __nv_bfloat162 l2;
    l2.x = __float2bfloat16(x - __bfloat162float(hx));
    l2.y = __float2bfloat16(y - __bfloat162float(hy));
    hi = *(uint32_t*)&h2;
    lo = *(uint32_t*)&l2;
}

// ---------------------------------------------------------------------------
// Split fp32 -> bf16 hi/lo (elementwise)
// ---------------------------------------------------------------------------
__global__ void split2_kernel(const float* __restrict__ x, __nv_bfloat16* __restrict__ hi,
                              __nv_bfloat16* __restrict__ lo, int n4) {
    int i = blockIdx.x * blockDim.x + threadIdx.x;
    if (i >= n4) return;
    float4 v = ((const float4*)x)[i];
    uint32_t h0, l0, h1, l1;
    split_pack(v.x, v.y, h0, l0);
    split_pack(v.z, v.w, h1, l1);
    ((uint2*)hi)[i] = make_uint2(h0, h1);
    ((uint2*)lo)[i] = make_uint2(l0, l1);
}

// ---------------------------------------------------------------------------
// Transpose + split: W[K][N] fp32 -> T_hi/T_lo[N][GK] bf16 (rows offset by roff)
// ---------------------------------------------------------------------------
__global__ void tsplit_kernel(const float* __restrict__ W, __nv_bfloat16* __restrict__ Thi,
                              __nv_bfloat16* __restrict__ Tlo, int N, int roff) {
    __shared__ float t[32][33];
    int n0 = blockIdx.x * 32, k0 = blockIdx.y * 32;
    int tx = threadIdx.x, ty = threadIdx.y;
#pragma unroll
    for (int r = 0; r < 4; r++)
        t[ty + 8 * r][tx] = W[(size_t)(k0 + ty + 8 * r) * N + n0 + tx];
    __syncthreads();
#pragma unroll
    for (int r = 0; r < 4; r++) {
        int rr = ty + 8 * r;
        float x = t[tx][rr];
        __nv_bfloat16 h = __float2bfloat16(x);
        size_t o = (size_t)(roff + n0 + rr) * GK + k0 + tx;
        Thi[o] = h;
        Tlo[o] = __float2bfloat16(x - __bfloat162float(h));
    }
}

// ---------------------------------------------------------------------------
// mma.sync split-bf16 GEMM. MODE 0: plain fp32 C store. MODE 1: fused
// RoPE + bf16-split epilogue writing q/k/v operand arrays directly.
// ---------------------------------------------------------------------------
#define TILE_B   10240
#define STAGE_B  (4 * TILE_B)
#define GEMM_SMEM (2 * STAGE_B)

__device__ __forceinline__ void gemm_issue(const __nv_bfloat16* const* srcs,
                                           uint32_t sbase, int stage, int k0, int tid) {
#pragma unroll
    for (int t = 0; t < 4; t++) {
        const __nv_bfloat16* s = srcs[t] + k0;
        uint32_t dstb = sbase + stage * STAGE_B + t * TILE_B;
#pragma unroll
        for (int c2 = 0; c2 < 2; c2++) {
            int c = c2 * 256 + tid;
            int row = c >> 2, sub = c & 3;
            CP_ASYNC16(dstb + row * 80 + sub * 16, s + (size_t)row * GK + sub * 8);
        }
    }
    CP_COMMIT();
}

template <int MODE>
__global__ __launch_bounds__(256, 2) void gemm_mma(
    const __nv_bfloat16* __restrict__ Ahi, const __nv_bfloat16* __restrict__ Alo,
    const __nv_bfloat16* __restrict__ Bhi, const __nv_bfloat16* __restrict__ Blo,
    float* __restrict__ C, int N) {
    extern __shared__ char smem[];
    const uint32_t sbase = smem_u32(smem);
    const int tid = threadIdx.x;
    const int wid = tid >> 5, lane = tid & 31;
    const int wm = wid & 3, wn = wid >> 2;
    const int bm = blockIdx.y, bn = blockIdx.x;

    const __nv_bfloat16* srcs[4] = {
        Ahi + (size_t)bm * 128 * GK, Alo + (size_t)bm * 128 * GK,
        Bhi + (size_t)bn * 128 * GK, Blo + (size_t)bn * 128 * GK};

    float acc[2][8][4];
#pragma unroll
    for (int i = 0; i < 2; i++)
#pragma unroll
        for (int j = 0; j < 8; j++)
#pragma unroll
            for (int k = 0; k < 4; k++) acc[i][j][k] = 0.f;

    const int NIT = GK / 32;
    gemm_issue(srcs, sbase, 0, 0, tid);

    const int a_row = wm * 32 + (lane & 15);
    const int a_koff = (lane >> 4) << 3;
    const int b_row = wn * 64 + (lane & 7) + ((lane >> 4) << 3);
    const int b_koff = ((lane >> 3) & 1) << 3;

    for (int i = 0; i < NIT; i++) {
        if (i + 1 < NIT) gemm_issue(srcs, sbase, (i + 1) & 1, (i + 1) * 32, tid);
        if (i + 1 < NIT) { CP_WAIT1(); } else { CP_WAIT0(); }
        __syncthreads();

        uint32_t s_ahi = sbase + (i & 1) * STAGE_B;
        uint32_t s_alo = s_ahi + TILE_B;
        uint32_t s_bhi = s_ahi + 2 * TILE_B;
        uint32_t s_blo = s_ahi + 3 * TILE_B;

#pragma unroll
        for (int ks = 0; ks < 2; ks++) {
            int kc = ks * 16;
            uint32_t ah[2][4], al[2][4];
#pragma unroll
            for (int mf = 0; mf < 2; mf++) {
                uint32_t ro = (a_row + mf * 16) * 80 + (kc + a_koff) * 2;
                LDMX4(ah[mf], s_ahi + ro);
                LDMX4(al[mf], s_alo + ro);
            }
#pragma unroll
            for (int nh = 0; nh < 2; nh++) {
                uint32_t bh[4][2], bl[4][2];
#pragma unroll
                for (int g = 0; g < 2; g++) {
                    uint32_t r[4];
                    uint32_t ro = (b_row + nh * 32 + g * 16) * 80 + (kc + b_koff) * 2;
                    LDMX4(r, s_bhi + ro);
                    bh[g * 2][0] = r[0]; bh[g * 2][1] = r[1];
                    bh[g * 2 + 1][0] = r[2]; bh[g * 2 + 1][1] = r[3];
                    LDMX4(r, s_blo + ro);
                    bl[g * 2][0] = r[0]; bl[g * 2][1] = r[1];
                    bl[g * 2 + 1][0] = r[2]; bl[g * 2 + 1][1] = r[3];
                }
#pragma unroll
                for (int mf = 0; mf < 2; mf++)
#pragma unroll
                    for (int nf = 0; nf < 4; nf++) {
                        float* d = acc[mf][nh * 4 + nf];
                        mma_bf16(d, ah[mf], bh[nf]);
                        mma_bf16(d, ah[mf], bl[nf]);
                        mma_bf16(d, al[mf], bh[nf]);
                    }
            }
        }
        __syncthreads();
    }

    const int er = lane >> 2, ec = (lane & 3) * 2;
    if (MODE == 0) {
#pragma unroll
        for (int mf = 0; mf < 2; mf++) {
            float* c0 = C + (size_t)(bm * 128 + wm * 32 + mf * 16 + er) * N + bn * 128 + wn * 64 + ec;
#pragma unroll
            for (int nf = 0; nf < 8; nf++) {
                float* cp = c0 + nf * 8;
                cp[0] = acc[mf][nf][0];
                cp[1] = acc[mf][nf][1];
                cp[8 * (size_t)N + 0] = acc[mf][nf][2];
                cp[8 * (size_t)N + 1] = acc[mf][nf][3];
            }
        }
    } else {
        // fused RoPE + split epilogue into q/k/v operand arrays
        const float LOGT = 13.122363377404328f;   // ln(500000)
#pragma unroll
        for (int nf = 0; nf < 8; nf++) {
            int n = bn * 128 + wn * 64 + nf * 8 + ec;
            bool dorope = (n < 2560);
            float f0 = 0.f, f1 = 0.f;
            if (dorope) {
                int j0 = n & 31;
                f0 = expf(-(float)j0 * (LOGT / 32.f));
                f1 = expf(-(float)(j0 + 1) * (LOGT / 32.f));
            }
#pragma unroll
            for (int mf = 0; mf < 2; mf++) {
                int m = bm * 128 + wm * 32 + mf * 16 + er;
#pragma unroll
                for (int rr = 0; rr < 2; rr++) {
                    int row = m + rr * 8;
                    float v0 = acc[mf][nf][rr * 2], v1 = acc[mf][nf][rr * 2 + 1];
                    float y0 = v0, y1 = v1;
                    if (dorope) {
                        float t = (float)row;
                        float s0, c0, s1, c1;
                        sincosf(t * f0, &s0, &c0);
                        sincosf(t * f1, &s1, &c1);
                        y0 = v0 * c0 - v1 * s0;
                        y1 = v1 * c1 + v0 * s1;
                    }
                    uint32_t hw, lw;
                    split_pack(y0, y1, hw, lw);
                    if (n < 2048) {
                        size_t idx = ((size_t)row * 2048 + n) >> 1;
                        ((uint32_t*)g_qh)[idx] = hw;
                        ((uint32_t*)g_ql)[idx] = lw;
                    } else if (n < 2560) {
                        size_t idx = ((size_t)row * 512 + (n - 2048)) >> 1;
                        ((uint32_t*)g_kh)[idx] = hw;
                        ((uint32_t*)g_kl)[idx] = lw;
                    } else {
                        size_t idx = ((size_t)row * 512 + (n - 2560)) >> 1;
                        ((uint32_t*)g_vh)[idx] = hw;
                        ((uint32_t*)g_vl)[idx] = lw;
                    }
                }
            }
        }
    }
}

// ---------------------------------------------------------------------------
// Tensor-core flash attention (split-bf16), 128 q-rows/CTA, 256 threads,
// 8 warps x 16 rows. Smem: Q(hi,lo) 32KB + 2 stages of Kh|Kl|Vh|Vl 32KB.
// ---------------------------------------------------------------------------
#define AT_SMEM (32768 + 2 * 32768)
#define SWZ(row, cb) ((uint32_t)((row) * 128 + ((cb) ^ (((row) & 7) << 4))))

__device__ __forceinline__ void attn_issue_kv(uint32_t base, int jb, int kvh, int tid) {
#pragma unroll
    for (int it = 0; it < 8; it++) {
        const int arr = it >> 1;
        const __nv_bfloat16* p = (arr == 0) ? g_kh : (arr == 1) ? g_kl
                               : (arr == 2) ? g_vh : g_vl;
        int idx = (it & 1) * 256 + tid;
        int row = idx >> 3, sub = idx & 7;
        size_t off = (size_t)(jb * 64 + row) * 512 + kvh * 64 + sub * 8;
        CP_ASYNC16(base + arr * 8192 + SWZ(row, sub * 16), p + off);
    }
    CP_COMMIT();
}

__global__ __launch_bounds__(256) void attn_mma(void) {
    extern __shared__ char smem[];
    const uint32_t sb = smem_u32(smem);
    const int tid = threadIdx.x, wid = tid >> 5, lane = tid & 31;
    const int qb = gridDim.x - 1 - blockIdx.x;   // heavy blocks first
    const int h = blockIdx.y, kvh = h >> 2;
    const uint32_t sKV = sb + 32768;
    const int jbmax = 2 * qb + 1;

    // Q loads (hi at sb, lo at sb+16KB) + first KV stage = group 0
#pragma unroll
    for (int it = 0; it < 8; it++) {
        const int arr = it >> 2;
        const __nv_bfloat16* p = arr ? g_ql : g_qh;
        int idx = (it & 3) * 256 + tid;
        int row = idx >> 3, sub = idx & 7;
        size_t off = (size_t)(qb * 128 + row) * 2048 + h * 64 + sub * 8;
        CP_ASYNC16(sb + arr * 16384 + SWZ(row, sub * 16), p + off);
    }
    attn_issue_kv(sKV, 0, kvh, tid);                 // commits group 0 (with Q)
    attn_issue_kv(sKV + 32768, 1, kvh, tid);         // group 1 (jbmax >= 1 always)

    float m0 = -1e30f, m1 = -1e30f, l0 = 0.f, l1 = 0.f;
    float o[8][4];
#pragma unroll
    for (int j = 0; j < 8; j++)
#pragma unroll
        for (int k = 0; k < 4; k++) o[j][k] = 0.f;

    uint32_t qfh[4][4], qfl[4][4];

    const int a_row = wid * 16 + (lane & 15);
    const int a_koff = (lane >> 4) << 3;
    const int b_row0 = (lane & 7) + ((lane >> 4) << 3);
    const int b_koff = ((lane >> 3) & 1) << 3;
    const int v_row0 = lane & 15;
    const int v_coff = (lane >> 4) << 3;

    for (int jb = 0; jb <= jbmax; jb++) {
        if (jb == 0) {
            CP_WAIT1();
        } else {
            if (jb + 1 <= jbmax) {
                attn_issue_kv(sKV + ((jb + 1) & 1) * 32768, jb + 1, kvh, tid);
                CP_WAIT1();
            } else { CP_WAIT0(); }
        }
        __syncthreads();

        if (jb == 0) {   // Q frags (once)
#pragma unroll
            for (int ks = 0; ks < 4; ks++) {
                uint32_t ro = SWZ(a_row, (ks * 16 + a_koff) * 2);
                LDMX4(qfh[ks], sb + ro);
                LDMX4(qfl[ks], sb + 16384 + ro);
            }
        }

        const uint32_t st = sKV + (jb & 1) * 32768;

        // ---- S = Q K^T (split) ----
        float s[8][4];
#pragma unroll
        for (int j = 0; j < 8; j++)
#pragma unroll
            for (int k = 0; k < 4; k++) s[j][k] = 0.f;
#pragma unroll
        for (int ks = 0; ks < 4; ks++) {
#pragma unroll
            for (int nb = 0; nb < 4; nb++) {
                uint32_t kbh[4], kbl[4];
                uint32_t ro = SWZ(nb * 16 + b_row0, (ks * 16 + b_koff) * 2);
                LDMX4(kbh, st + ro);
                LDMX4(kbl, st + 8192 + ro);
                mma_bf16(s[2 * nb], qfh[ks], kbh);
                mma_bf16(s[2 * nb], qfh[ks], kbl);
                mma_bf16(s[2 * nb], qfl[ks], kbh);
                mma_bf16(s[2 * nb + 1], qfh[ks], kbh + 2);
                mma_bf16(s[2 * nb + 1], qfh[ks], kbl + 2);
                mma_bf16(s[2 * nb + 1], qfl[ks], kbh + 2);
            }
        }

        // ---- scale + causal mask (only last two KV blocks can clip) ----
        const float scale = 0.125f;
        if (jb >= 2 * qb) {
            int rp0 = qb * 128 + wid * 16 + (lane >> 2);
            int cb0 = jb * 64 + (lane & 3) * 2;
#pragma unroll
            for (int j = 0; j < 8; j++) {
                int cp = cb0 + j * 8;
                s[j][0] = s[j][0] * scale + ((cp > rp0) ? -1e9f : 0.f);
                s[j][1] = s[j][1] * scale + ((cp + 1 > rp0) ? -1e9f : 0.f);
                s[j][2] = s[j][2] * scale + ((cp > rp0 + 8) ? -1e9f : 0.f);
                s[j][3] = s[j][3] * scale + ((cp + 1 > rp0 + 8) ? -1e9f : 0.f);
            }
        } else {
#pragma unroll
            for (int j = 0; j < 8; j++)
#pragma unroll
                for (int k = 0; k < 4; k++) s[j][k] *= scale;
        }

        // ---- online softmax ----
        float mx0 = -1e30f, mx1 = -1e30f;
#pragma unroll
        for (int j = 0; j < 8; j++) {
            mx0 = fmaxf(mx0, fmaxf(s[j][0], s[j][1]));
            mx1 = fmaxf(mx1, fmaxf(s[j][2], s[j][3]));
        }
        mx0 = fmaxf(mx0, __shfl_xor_sync(0xffffffffu, mx0, 1));
        mx0 = fmaxf(mx0, __shfl_xor_sync(0xffffffffu, mx0, 2));
        mx1 = fmaxf(mx1, __shfl_xor_sync(0xffffffffu, mx1, 1));
        mx1 = fmaxf(mx1, __shfl_xor_sync(0xffffffffu, mx1, 2));
        float nm0 = fmaxf(m0, mx0), nm1 = fmaxf(m1, mx1);
        float al0 = __expf(m0 - nm0), al1 = __expf(m1 - nm1);
        m0 = nm0; m1 = nm1;
        float rs0 = 0.f, rs1 = 0.f;
#pragma unroll
        for (int j = 0; j < 8; j++) {
            s[j][0] = __expf(s[j][0] - nm0);
            s[j][1] = __expf(s[j][1] - nm0);
            s[j][2] = __expf(s[j][2] - nm1);
            s[j][3] = __expf(s[j][3] - nm1);
            rs0 += s[j][0] + s[j][1];
            rs1 += s[j][2] + s[j][3];
        }
        l0 = l0 * al0 + rs0;
        l1 = l1 * al1 + rs1;
#pragma unroll
        for (int j = 0; j < 8; j++) {
            o[j][0] *= al0; o[j][1] *= al0;
            o[j][2] *= al1; o[j][3] *= al1;
        }

        // ---- O += P V (split) ----
#pragma unroll
        for (int ks = 0; ks < 4; ks++) {
            uint32_t pah[4], pal[4];
            split_pack(s[2 * ks][0], s[2 * ks][1], pah[0], pal[0]);
            split_pack(s[2 * ks][2], s[2 * ks][3], pah[1], pal[1]);
            split_pack(s[2 * ks + 1][0], s[2 * ks + 1][1], pah[2], pal[2]);
            split_pack(s[2 * ks + 1][2], s[2 * ks + 1][3], pah[3], pal[3]);
#pragma unroll
            for (int db = 0; db < 4; db++) {
                uint32_t vbh[4], vbl[4];
                uint32_t ro = SWZ(ks * 16 + v_row0, (db * 16 + v_coff) * 2);
                LDMX4T(vbh, st + 16384 + ro);
                LDMX4T(vbl, st + 24576 + ro);
                mma_bf16(o[2 * db], pah, vbh);
                mma_bf16(o[2 * db], pah, vbl);
                mma_bf16(o[2 * db], pal, vbh);
                mma_bf16(o[2 * db + 1], pah, vbh + 2);
                mma_bf16(o[2 * db + 1], pah, vbl + 2);
                mma_bf16(o[2 * db + 1], pal, vbh + 2);
            }
        }
        __syncthreads();
    }

    // ---- epilogue: finish l, normalize, split-write ----
    l0 += __shfl_xor_sync(0xffffffffu, l0, 1);
    l0 += __shfl_xor_sync(0xffffffffu, l0, 2);
    l1 += __shfl_xor_sync(0xffffffffu, l1, 1);
    l1 += __shfl_xor_sync(0xffffffffu, l1, 2);
    float inv0 = 1.f / l0, inv1 = 1.f / l1;
    int r0 = qb * 128 + wid * 16 + (lane >> 2);
    int cb = h * 64 + (lane & 3) * 2;
#pragma unroll
    for (int j = 0; j < 8; j++) {
        int c = cb + j * 8;
        uint32_t hw, lw;
        split_pack(o[j][0] * inv0, o[j][1] * inv0, hw, lw);
        ((uint32_t*)g_attn_hi)[((size_t)r0 * 2048 + c) >> 1] = hw;
        ((uint32_t*)g_attn_lo)[((size_t)r0 * 2048 + c) >> 1] = lw;
        split_pack(o[j][2] * inv1, o[j][3] * inv1, hw, lw);
        ((uint32_t*)g_attn_hi)[(((size_t)r0 + 8) * 2048 + c) >> 1] = hw;
        ((uint32_t*)g_attn_lo)[(((size_t)r0 + 8) * 2048 + c) >> 1] = lw;
    }
}

// ---------------------------------------------------------------------------
extern "C" void kernel_launch(void* const* d_in, const int* in_sizes, int n_in,
                              void* d_out, int out_size) {
    const float* hidden = (const float*)d_in[0];
    const float* Wq = (const float*)d_in[2];
    const float* Wk = (const float*)d_in[3];
    const float* Wv = (const float*)d_in[4];
    const float* Wo = (const float*)d_in[5];
    float* out = (float*)d_out;

    __nv_bfloat16 *hh, *hl, *wqh, *wql, *woh, *wol, *ah, *al;
    cudaGetSymbolAddress((void**)&hh, g_hid_hi);
    cudaGetSymbolAddress((void**)&hl, g_hid_lo);
    cudaGetSymbolAddress((void**)&wqh, g_wqkvT_hi);
    cudaGetSymbolAddress((void**)&wql, g_wqkvT_lo);
    cudaGetSymbolAddress((void**)&woh, g_woT_hi);
    cudaGetSymbolAddress((void**)&wol, g_woT_lo);
    cudaGetSymbolAddress((void**)&ah, g_attn_hi);
    cudaGetSymbolAddress((void**)&al, g_attn_lo);

    cudaFuncSetAttribute(gemm_mma<0>, cudaFuncAttributeMaxDynamicSharedMemorySize, GEMM_SMEM);
    cudaFuncSetAttribute(gemm_mma<1>, cudaFuncAttributeMaxDynamicSharedMemorySize, GEMM_SMEM);
    cudaFuncSetAttribute(attn_mma, cudaFuncAttributeMaxDynamicSharedMemorySize, AT_SMEM);

    // 1) operand prep
    split2_kernel<<<(SEQL * HID / 4 + 255) / 256, 256>>>(hidden, hh, hl, SEQL * HID / 4);
    tsplit_kernel<<<dim3(2048 / 32, GK / 32), dim3(32, 8)>>>(Wq, wqh, wql, 2048, 0);
    tsplit_kernel<<<dim3(512 / 32, GK / 32), dim3(32, 8)>>>(Wk, wqh, wql, 512, 2048);
    tsplit_kernel<<<dim3(512 / 32, GK / 32), dim3(32, 8)>>>(Wv, wqh, wql, 512, 2560);
    tsplit_kernel<<<dim3(2048 / 32, GK / 32), dim3(32, 8)>>>(Wo, woh, wol, 2048, 0);

    // 2) fused QKV projection + RoPE + split epilogue
    gemm_mma<1><<<dim3(QKVN / 128, SEQL / 128), 256, GEMM_SMEM>>>(hh, hl, wqh, wql, nullptr, QKVN);

    // 3) tensor-core causal GQA flash attention (128 q-rows/CTA)
    attn_mma<<<dim3(SEQL / 128, NH), 256, AT_SMEM>>>();

    // 4) O-projection
    gemm_mma<0><<<dim3(HID / 128, SEQL / 128), 256, GEMM_SMEM>>>(ah, al, woh, wol, out, HID);
}

// round 6
// speedup vs baseline: 1.0556x; 1.0556x over previous
#include <cuda_runtime.h>
#include <cuda_bf16.h>
#include <cstdint>
#include <math.h>

#define SEQL 2048
#define HID  2048
#define NH   32
#define NKV  8
#define HD   64
#define QKVN 3072
#define GK   2048

// ---------------------------------------------------------------------------
// Scratch (device globals; no allocations allowed)
// ---------------------------------------------------------------------------
__device__ float          g_qkvp[3 * SEQL * QKVN];      // split-K partials (75MB)
__device__ __nv_bfloat16  g_hid_hi[SEQL * HID];
__device__ __nv_bfloat16  g_hid_lo[SEQL * HID];
__device__ __nv_bfloat16  g_wqkvT_hi[QKVN * GK];
__device__ __nv_bfloat16  g_wqkvT_lo[QKVN * GK];
__device__ __nv_bfloat16  g_woT_hi[HID * GK];
__device__ __nv_bfloat16  g_woT_lo[HID * GK];
__device__ __nv_bfloat16  g_attn_hi[SEQL * HID];
__device__ __nv_bfloat16  g_attn_lo[SEQL * HID];
__device__ __nv_bfloat16  g_qh[SEQL * NH * HD];
__device__ __nv_bfloat16  g_ql[SEQL * NH * HD];
__device__ __nv_bfloat16  g_kh[SEQL * NKV * HD];
__device__ __nv_bfloat16  g_kl[SEQL * NKV * HD];
__device__ __nv_bfloat16  g_vh[SEQL * NKV * HD];
__device__ __nv_bfloat16  g_vl[SEQL * NKV * HD];

// ---------------------------------------------------------------------------
// PTX helpers (baseline sm_80+ only)
// ---------------------------------------------------------------------------
__device__ __forceinline__ uint32_t smem_u32(const void* p) {
    uint32_t a;
    asm("{ .reg .u64 t; cvta.to.shared.u64 t, %1; cvt.u32.u64 %0, t; }" : "=r"(a) : "l"(p));
    return a;
}
#define LDMX4(r, addr) \
    asm volatile("ldmatrix.sync.aligned.m8n8.x4.shared.b16 {%0,%1,%2,%3}, [%4];" \
        : "=r"((r)[0]), "=r"((r)[1]), "=r"((r)[2]), "=r"((r)[3]) : "r"(addr))
#define LDMX4T(r, addr) \
    asm volatile("ldmatrix.sync.aligned.m8n8.x4.trans.shared.b16 {%0,%1,%2,%3}, [%4];" \
        : "=r"((r)[0]), "=r"((r)[1]), "=r"((r)[2]), "=r"((r)[3]) : "r"(addr))
#define CP_ASYNC16(dst, src) \
    asm volatile("cp.async.cg.shared.global [%0], [%1], 16;" :: "r"(dst), "l"(src))
#define CP_COMMIT() asm volatile("cp.async.commit_group;")
#define CP_WAIT1()  asm volatile("cp.async.wait_group 1;")
#define CP_WAIT0()  asm volatile("cp.async.wait_group 0;")

__device__ __forceinline__ void mma_bf16(float* d, const uint32_t* a, const uint32_t* b) {
    asm volatile("mma.sync.aligned.m16n8k16.row.col.f32.bf16.bf16.f32 "
        "{%0,%1,%2,%3}, {%4,%5,%6,%7}, {%8,%9}, {%0,%1,%2,%3};"
        : "+f"(d[0]), "+f"(d[1]), "+f"(d[2]), "+f"(d[3])
        : "r"(a[0]), "r"(a[1]), "r"(a[2]), "r"(a[3]), "r"(b[0]), "r"(b[1]));
}

__device__ __forceinline__ void split_pack(float x, float y, uint32_t& hi, uint32_t& lo) {
    __nv_bfloat16 hx = __float2bfloat16(x), hy = __float2bfloat16(y);
    __nv_bfloat162 h2; h2.x = hx; h2.y = hy;
    __nv_bfloat162 l2;
    l2.x = __float2bfloat16(x - __bfloat162float(hx));
    l2.y = __float2bfloat16(y - __bfloat162float(hy));
    hi = *(uint32_t*)&h2;
    lo = *(uint32_t*)&l2;
}

// ---------------------------------------------------------------------------
// Split fp32 -> bf16 hi/lo (elementwise)
// ---------------------------------------------------------------------------
__global__ void split2_kernel(const float* __restrict__ x, __nv_bfloat16* __restrict__ hi,
                              __nv_bfloat16* __restrict__ lo, int n4) {
    int i = blockIdx.x * blockDim.x + threadIdx.x;
    if (i >= n4) return;
    float4 v = ((const float4*)x)[i];
    uint32_t h0, l0, h1, l1;
    split_pack(v.x, v.y, h0, l0);
    split_pack(v.z, v.w, h1, l1);
    ((uint2*)hi)[i] = make_uint2(h0, h1);
    ((uint2*)lo)[i] = make_uint2(l0, l1);
}

// ---------------------------------------------------------------------------
// Transpose + split: W[K][N] fp32 -> T_hi/T_lo[N][GK] bf16 (rows offset by roff)
// ---------------------------------------------------------------------------
__global__ void tsplit_kernel(const float* __restrict__ W, __nv_bfloat16* __restrict__ Thi,
                              __nv_bfloat16* __restrict__ Tlo, int N, int roff) {
    __shared__ float t[32][33];
    int n0 = blockIdx.x * 32, k0 = blockIdx.y * 32;
    int tx = threadIdx.x, ty = threadIdx.y;
#pragma unroll
    for (int r = 0; r < 4; r++)
        t[ty + 8 * r][tx] = W[(size_t)(k0 + ty + 8 * r) * N + n0 + tx];
    __syncthreads();
#pragma unroll
    for (int r = 0; r < 4; r++) {
        int rr = ty + 8 * r;
        float x = t[tx][rr];
        __nv_bfloat16 h = __float2bfloat16(x);
        size_t o = (size_t)(roff + n0 + rr) * GK + k0 + tx;
        Thi[o] = h;
        Tlo[o] = __float2bfloat16(x - __bfloat162float(h));
    }
}

// ---------------------------------------------------------------------------
// mma.sync split-bf16 GEMM. SPLITS=1: full K, plain store.
// SPLITS=3: blockIdx.z selects a K range; partial stored at C + z*2048*N.
// ---------------------------------------------------------------------------
#define TILE_B   10240
#define STAGE_B  (4 * TILE_B)
#define GEMM_SMEM (2 * STAGE_B)

__device__ __forceinline__ void gemm_issue(const __nv_bfloat16* const* srcs,
                                           uint32_t sbase, int stage, int k0, int tid) {
#pragma unroll
    for (int t = 0; t < 4; t++) {
        const __nv_bfloat16* s = srcs[t] + k0;
        uint32_t dstb = sbase + stage * STAGE_B + t * TILE_B;
#pragma unroll
        for (int c2 = 0; c2 < 2; c2++) {
            int c = c2 * 256 + tid;
            int row = c >> 2, sub = c & 3;
            CP_ASYNC16(dstb + row * 80 + sub * 16, s + (size_t)row * GK + sub * 8);
        }
    }
    CP_COMMIT();
}

template <int SPLITS>
__global__ __launch_bounds__(256, 2) void gemm_mma(
    const __nv_bfloat16* __restrict__ Ahi, const __nv_bfloat16* __restrict__ Alo,
    const __nv_bfloat16* __restrict__ Bhi, const __nv_bfloat16* __restrict__ Blo,
    float* __restrict__ C, int N) {
    extern __shared__ char smem[];
    const uint32_t sbase = smem_u32(smem);
    const int tid = threadIdx.x;
    const int wid = tid >> 5, lane = tid & 31;
    const int wm = wid & 3, wn = wid >> 2;
    const int bm = blockIdx.y, bn = blockIdx.x;

    int i0 = 0, i1 = GK / 32;
    if (SPLITS == 3) {
        const int bounds[4] = {0, 22, 43, 64};
        i0 = bounds[blockIdx.z];
        i1 = bounds[blockIdx.z + 1];
        C += (size_t)blockIdx.z * 2048 * N;
    }
    const int nit = i1 - i0;

    const __nv_bfloat16* srcs[4] = {
        Ahi + (size_t)bm * 128 * GK, Alo + (size_t)bm * 128 * GK,
        Bhi + (size_t)bn * 128 * GK, Blo + (size_t)bn * 128 * GK};

    float acc[2][8][4];
#pragma unroll
    for (int i = 0; i < 2; i++)
#pragma unroll
        for (int j = 0; j < 8; j++)
#pragma unroll
            for (int k = 0; k < 4; k++) acc[i][j][k] = 0.f;

    gemm_issue(srcs, sbase, 0, i0 * 32, tid);

    const int a_row = wm * 32 + (lane & 15);
    const int a_koff = (lane >> 4) << 3;
    const int b_row = wn * 64 + (lane & 7) + ((lane >> 4) << 3);
    const int b_koff = ((lane >> 3) & 1) << 3;

    for (int it = 0; it < nit; it++) {
        if (it + 1 < nit) {
            gemm_issue(srcs, sbase, (it + 1) & 1, (i0 + it + 1) * 32, tid);
            CP_WAIT1();
        } else { CP_WAIT0(); }
        __syncthreads();

        uint32_t s_ahi = sbase + (it & 1) * STAGE_B;
        uint32_t s_alo = s_ahi + TILE_B;
        uint32_t s_bhi = s_ahi + 2 * TILE_B;
        uint32_t s_blo = s_ahi + 3 * TILE_B;

#pragma unroll
        for (int ks = 0; ks < 2; ks++) {
            int kc = ks * 16;
            uint32_t ah[2][4], al[2][4];
#pragma unroll
            for (int mf = 0; mf < 2; mf++) {
                uint32_t ro = (a_row + mf * 16) * 80 + (kc + a_koff) * 2;
                LDMX4(ah[mf], s_ahi + ro);
                LDMX4(al[mf], s_alo + ro);
            }
#pragma unroll
            for (int nh = 0; nh < 2; nh++) {
                uint32_t bh[4][2], bl[4][2];
#pragma unroll
                for (int g = 0; g < 2; g++) {
                    uint32_t r[4];
                    uint32_t ro = (b_row + nh * 32 + g * 16) * 80 + (kc + b_koff) * 2;
                    LDMX4(r, s_bhi + ro);
                    bh[g * 2][0] = r[0]; bh[g * 2][1] = r[1];
                    bh[g * 2 + 1][0] = r[2]; bh[g * 2 + 1][1] = r[3];
                    LDMX4(r, s_blo + ro);
                    bl[g * 2][0] = r[0]; bl[g * 2][1] = r[1];
                    bl[g * 2 + 1][0] = r[2]; bl[g * 2 + 1][1] = r[3];
                }
#pragma unroll
                for (int mf = 0; mf < 2; mf++)
#pragma unroll
                    for (int nf = 0; nf < 4; nf++) {
                        float* d = acc[mf][nh * 4 + nf];
                        mma_bf16(d, ah[mf], bh[nf]);
                        mma_bf16(d, ah[mf], bl[nf]);
                        mma_bf16(d, al[mf], bh[nf]);
                    }
            }
        }
        __syncthreads();
    }

    const int er = lane >> 2, ec = (lane & 3) * 2;
#pragma unroll
    for (int mf = 0; mf < 2; mf++) {
        float* c0 = C + (size_t)(bm * 128 + wm * 32 + mf * 16 + er) * N + bn * 128 + wn * 64 + ec;
#pragma unroll
        for (int nf = 0; nf < 8; nf++) {
            float* cp = c0 + nf * 8;
            cp[0] = acc[mf][nf][0];
            cp[1] = acc[mf][nf][1];
            cp[8 * (size_t)N + 0] = acc[mf][nf][2];
            cp[8 * (size_t)N + 1] = acc[mf][nf][3];
        }
    }
}

// ---------------------------------------------------------------------------
// Fused split-K reduce + RoPE + bf16-split of q/k/v.
// ---------------------------------------------------------------------------
__global__ void rope_split_kernel(const float* __restrict__ P) {
    int p = blockIdx.x * blockDim.x + threadIdx.x;
    if (p >= SEQL * 1536) return;
    int s = p / 1536, col = (p % 1536) * 2;
    const size_t PART = (size_t)SEQL * QKVN;
    size_t base = (size_t)s * QKVN + col;
    float x0 = P[base] + P[base + PART] + P[base + 2 * PART];
    float x1 = P[base + 1] + P[base + 1 + PART] + P[base + 1 + 2 * PART];
    float y0, y1;
    if (col < 2560) {   // q + k get rope
        int j0 = col & 31;
        const float LOGT = 13.122363377404328f;   // ln(500000)
        float f0 = expf(-(float)j0 * (LOGT / 32.f));
        float f1 = expf(-(float)(j0 + 1) * (LOGT / 32.f));
        float t = (float)s;
        float s0, c0, s1, c1;
        sincosf(t * f0, &s0, &c0);
        sincosf(t * f1, &s1, &c1);
        y0 = x0 * c0 - x1 * s0;
        y1 = x1 * c1 + x0 * s1;
    } else { y0 = x0; y1 = x1; }
    uint32_t hw, lw;
    split_pack(y0, y1, hw, lw);
    if (col < 2048) {
        int idx = (s * 2048 + col) >> 1;
        ((uint32_t*)g_qh)[idx] = hw;
        ((uint32_t*)g_ql)[idx] = lw;
    } else if (col < 2560) {
        int idx = (s * 512 + col - 2048) >> 1;
        ((uint32_t*)g_kh)[idx] = hw;
        ((uint32_t*)g_kl)[idx] = lw;
    } else {
        int idx = (s * 512 + col - 2560) >> 1;
        ((uint32_t*)g_vh)[idx] = hw;
        ((uint32_t*)g_vl)[idx] = lw;
    }
}

// ---------------------------------------------------------------------------
// Tensor-core flash attention (split-bf16), 64 q-rows/CTA, 128 threads (R4).
// Smem: Qh|Ql (8KB each) + 2 stages of Kh|Kl|Vh|Vl (8KB each). XOR swizzle.
// ---------------------------------------------------------------------------
#define AT_SMEM (16384 + 2 * 32768)
#define SWZ(row, cb) ((uint32_t)((row) * 128 + ((cb) ^ (((row) & 7) << 4))))

__device__ __forceinline__ void attn_issue_kv(uint32_t base, int jb, int kvh, int tid) {
#pragma unroll
    for (int it = 0; it < 16; it++) {
        const int arr = it >> 2;
        const __nv_bfloat16* p = (arr == 0) ? g_kh : (arr == 1) ? g_kl
                               : (arr == 2) ? g_vh : g_vl;
        int row = (it & 3) * 16 + (tid >> 3);
        int sub = tid & 7;
        size_t off = (size_t)(jb * 64 + row) * 512 + kvh * 64 + sub * 8;
        CP_ASYNC16(base + arr * 8192 + SWZ(row, sub * 16), p + off);
    }
    CP_COMMIT();
}

__global__ __launch_bounds__(128) void attn_mma(void) {
    extern __shared__ char smem[];
    const uint32_t sb = smem_u32(smem);
    const int tid = threadIdx.x, wid = tid >> 5, lane = tid & 31;
    const int qb = gridDim.x - 1 - blockIdx.x;   // heavy blocks first
    const int h = blockIdx.y, kvh = h >> 2;
    const uint32_t sKV = sb + 16384;

    // issue Q (into its own region) + first KV stage as group 0
#pragma unroll
    for (int it = 0; it < 8; it++) {
        const int arr = it >> 2;
        const __nv_bfloat16* p = arr ? g_ql : g_qh;
        int row = (it & 3) * 16 + (tid >> 3);
        int sub = tid & 7;
        size_t off = (size_t)(qb * 64 + row) * 2048 + h * 64 + sub * 8;
        CP_ASYNC16(sb + arr * 8192 + SWZ(row, sub * 16), p + off);
    }
    attn_issue_kv(sKV, 0, kvh, tid);            // commits group 0 (with Q)
    if (qb >= 1) attn_issue_kv(sKV + 32768, 1, kvh, tid);  // group 1

    float m0 = -1e30f, m1 = -1e30f, l0 = 0.f, l1 = 0.f;
    float o[8][4];
#pragma unroll
    for (int j = 0; j < 8; j++)
#pragma unroll
        for (int k = 0; k < 4; k++) o[j][k] = 0.f;

    uint32_t qfh[4][4], qfl[4][4];

    const int a_row = wid * 16 + (lane & 15);
    const int a_koff = (lane >> 4) << 3;
    const int b_row0 = (lane & 7) + ((lane >> 4) << 3);
    const int b_koff = ((lane >> 3) & 1) << 3;
    const int v_row0 = lane & 15;
    const int v_coff = (lane >> 4) << 3;

    for (int jb = 0; jb <= qb; jb++) {
        if (jb == 0) {
            if (qb >= 1) { CP_WAIT1(); } else { CP_WAIT0(); }
        } else {
            if (jb + 1 <= qb) {
                attn_issue_kv(sKV + ((jb + 1) & 1) * 32768, jb + 1, kvh, tid);
                CP_WAIT1();
            } else { CP_WAIT0(); }
        }
        __syncthreads();

        if (jb == 0) {   // Q frags (once)
#pragma unroll
            for (int ks = 0; ks < 4; ks++) {
                uint32_t ro = SWZ(a_row, (ks * 16 + a_koff) * 2);
                LDMX4(qfh[ks], sb + ro);
                LDMX4(qfl[ks], sb + 8192 + ro);
            }
        }

        const uint32_t st = sKV + (jb & 1) * 32768;

        // ---- S = Q K^T (split) ----
        float s[8][4];
#pragma unroll
        for (int j = 0; j < 8; j++)
#pragma unroll
            for (int k = 0; k < 4; k++) s[j][k] = 0.f;
#pragma unroll
        for (int ks = 0; ks < 4; ks++) {
#pragma unroll
            for (int nb = 0; nb < 4; nb++) {
                uint32_t kbh[4], kbl[4];
                uint32_t ro = SWZ(nb * 16 + b_row0, (ks * 16 + b_koff) * 2);
                LDMX4(kbh, st + ro);
                LDMX4(kbl, st + 8192 + ro);
                mma_bf16(s[2 * nb], qfh[ks], kbh);
                mma_bf16(s[2 * nb], qfh[ks], kbl);
                mma_bf16(s[2 * nb], qfl[ks], kbh);
                mma_bf16(s[2 * nb + 1], qfh[ks], kbh + 2);
                mma_bf16(s[2 * nb + 1], qfh[ks], kbl + 2);
                mma_bf16(s[2 * nb + 1], qfl[ks], kbh + 2);
            }
        }

        // ---- scale + causal mask ----
        const float scale = 0.125f;
        if (jb == qb) {
            int rp0 = wid * 16 + (lane >> 2);
#pragma unroll
            for (int j = 0; j < 8; j++) {
                int cp = j * 8 + (lane & 3) * 2;
                s[j][0] = s[j][0] * scale + ((cp > rp0) ? -1e9f : 0.f);
                s[j][1] = s[j][1] * scale + ((cp + 1 > rp0) ? -1e9f : 0.f);
                s[j][2] = s[j][2] * scale + ((cp > rp0 + 8) ? -1e9f : 0.f);
                s[j][3] = s[j][3] * scale + ((cp + 1 > rp0 + 8) ? -1e9f : 0.f);
            }
        } else {
#pragma unroll
            for (int j = 0; j < 8; j++)
#pragma unroll
                for (int k = 0; k < 4; k++) s[j][k] *= scale;
        }

        // ---- online softmax ----
        float mx0 = -1e30f, mx1 = -1e30f;
#pragma unroll
        for (int j = 0; j < 8; j++) {
            mx0 = fmaxf(mx0, fmaxf(s[j][0], s[j][1]));
            mx1 = fmaxf(mx1, fmaxf(s[j][2], s[j][3]));
        }
        mx0 = fmaxf(mx0, __shfl_xor_sync(0xffffffffu, mx0, 1));
        mx0 = fmaxf(mx0, __shfl_xor_sync(0xffffffffu, mx0, 2));
        mx1 = fmaxf(mx1, __shfl_xor_sync(0xffffffffu, mx1, 1));
        mx1 = fmaxf(mx1, __shfl_xor_sync(0xffffffffu, mx1, 2));
        float nm0 = fmaxf(m0, mx0), nm1 = fmaxf(m1, mx1);
        float al0 = __expf(m0 - nm0), al1 = __expf(m1 - nm1);
        m0 = nm0; m1 = nm1;
        float rs0 = 0.f, rs1 = 0.f;
#pragma unroll
        for (int j = 0; j < 8; j++) {
            s[j][0] = __expf(s[j][0] - nm0);
            s[j][1] = __expf(s[j][1] - nm0);
            s[j][2] = __expf(s[j][2] - nm1);
            s[j][3] = __expf(s[j][3] - nm1);
            rs0 += s[j][0] + s[j][1];
            rs1 += s[j][2] + s[j][3];
        }
        l0 = l0 * al0 + rs0;
        l1 = l1 * al1 + rs1;
#pragma unroll
        for (int j = 0; j < 8; j++) {
            o[j][0] *= al0; o[j][1] *= al0;
            o[j][2] *= al1; o[j][3] *= al1;
        }

        // ---- O += P V (split) ----
#pragma unroll
        for (int ks = 0; ks < 4; ks++) {
            uint32_t pah[4], pal[4];
            split_pack(s[2 * ks][0], s[2 * ks][1], pah[0], pal[0]);
            split_pack(s[2 * ks][2], s[2 * ks][3], pah[1], pal[1]);
            split_pack(s[2 * ks + 1][0], s[2 * ks + 1][1], pah[2], pal[2]);
            split_pack(s[2 * ks + 1][2], s[2 * ks + 1][3], pah[3], pal[3]);
#pragma unroll
            for (int db = 0; db < 4; db++) {
                uint32_t vbh[4], vbl[4];
                uint32_t ro = SWZ(ks * 16 + v_row0, (db * 16 + v_coff) * 2);
                LDMX4T(vbh, st + 16384 + ro);
                LDMX4T(vbl, st + 24576 + ro);
                mma_bf16(o[2 * db], pah, vbh);
                mma_bf16(o[2 * db], pah, vbl);
                mma_bf16(o[2 * db], pal, vbh);
                mma_bf16(o[2 * db + 1], pah, vbh + 2);
                mma_bf16(o[2 * db + 1], pah, vbl + 2);
                mma_bf16(o[2 * db + 1], pal, vbh + 2);
            }
        }
        __syncthreads();
    }

    // ---- epilogue ----
    l0 += __shfl_xor_sync(0xffffffffu, l0, 1);
    l0 += __shfl_xor_sync(0xffffffffu, l0, 2);
    l1 += __shfl_xor_sync(0xffffffffu, l1, 1);
    l1 += __shfl_xor_sync(0xffffffffu, l1, 2);
    float inv0 = 1.f / l0, inv1 = 1.f / l1;
    int r0 = qb * 64 + wid * 16 + (lane >> 2);
    int cb = h * 64 + (lane & 3) * 2;
#pragma unroll
    for (int j = 0; j < 8; j++) {
        int c = cb + j * 8;
        uint32_t hw, lw;
        split_pack(o[j][0] * inv0, o[j][1] * inv0, hw, lw);
        ((uint32_t*)g_attn_hi)[(r0 * 2048 + c) >> 1] = hw;
        ((uint32_t*)g_attn_lo)[(r0 * 2048 + c) >> 1] = lw;
        split_pack(o[j][2] * inv1, o[j][3] * inv1, hw, lw);
        ((uint32_t*)g_attn_hi)[((r0 + 8) * 2048 + c) >> 1] = hw;
        ((uint32_t*)g_attn_lo)[((r0 + 8) * 2048 + c) >> 1] = lw;
    }
}

// ---------------------------------------------------------------------------
extern "C" void kernel_launch(void* const* d_in, const int* in_sizes, int n_in,
                              void* d_out, int out_size) {
    const float* hidden = (const float*)d_in[0];
    const float* Wq = (const float*)d_in[2];
    const float* Wk = (const float*)d_in[3];
    const float* Wv = (const float*)d_in[4];
    const float* Wo = (const float*)d_in[5];
    float* out = (float*)d_out;

    float* qkvp;
    __nv_bfloat16 *hh, *hl, *wqh, *wql, *woh, *wol, *ah, *al;
    cudaGetSymbolAddress((void**)&qkvp, g_qkvp);
    cudaGetSymbolAddress((void**)&hh, g_hid_hi);
    cudaGetSymbolAddress((void**)&hl, g_hid_lo);
    cudaGetSymbolAddress((void**)&wqh, g_wqkvT_hi);
    cudaGetSymbolAddress((void**)&wql, g_wqkvT_lo);
    cudaGetSymbolAddress((void**)&woh, g_woT_hi);
    cudaGetSymbolAddress((void**)&wol, g_woT_lo);
    cudaGetSymbolAddress((void**)&ah, g_attn_hi);
    cudaGetSymbolAddress((void**)&al, g_attn_lo);

    cudaFuncSetAttribute(gemm_mma<1>, cudaFuncAttributeMaxDynamicSharedMemorySize, GEMM_SMEM);
    cudaFuncSetAttribute(gemm_mma<3>, cudaFuncAttributeMaxDynamicSharedMemorySize, GEMM_SMEM);
    cudaFuncSetAttribute(attn_mma, cudaFuncAttributeMaxDynamicSharedMemorySize, AT_SMEM);

    // 1) operand prep
    split2_kernel<<<(SEQL * HID / 4 + 255) / 256, 256>>>(hidden, hh, hl, SEQL * HID / 4);
    tsplit_kernel<<<dim3(2048 / 32, GK / 32), dim3(32, 8)>>>(Wq, wqh, wql, 2048, 0);
    tsplit_kernel<<<dim3(512 / 32, GK / 32), dim3(32, 8)>>>(Wk, wqh, wql, 512, 2048);
    tsplit_kernel<<<dim3(512 / 32, GK / 32), dim3(32, 8)>>>(Wv, wqh, wql, 512, 2560);
    tsplit_kernel<<<dim3(2048 / 32, GK / 32), dim3(32, 8)>>>(Wo, woh, wol, 2048, 0);

    // 2) fused QKV projection, split-K=3 (wave balance: 1152 CTAs of 1/3 work)
    gemm_mma<3><<<dim3(QKVN / 128, SEQL / 128, 3), 256, GEMM_SMEM>>>(hh, hl, wqh, wql, qkvp, QKVN);

    // 3) split-K reduce + RoPE + split q/k/v
    rope_split_kernel<<<(SEQL * 1536 + 255) / 256, 256>>>(qkvp);

    // 4) tensor-core causal GQA flash attention (64 q-rows/CTA, R4 config)
    attn_mma<<<dim3(SEQL / 64, NH), 128, AT_SMEM>>>();

    // 5) O-projection (256 CTAs = single wave, no split)
    gemm_mma<1><<<dim3(HID / 128, SEQL / 128), 256, GEMM_SMEM>>>(ah, al, woh, wol, out, HID);
}